// round 1
// baseline (speedup 1.0000x reference)
#include <cuda_runtime.h>

// HierarchicalSoftmax: out[b, c*320 + t] = (in[b]·Wtop[:,c] + btop[c]) + (in[b]·Wbot[t] + bbot[t])
// B=1024, NHID=128, NCLASSES=320, PER_CLASS=320, out = [1024, 102400] f32 (419 MB).
// Store-bandwidth bound; compute is ~82K FMA per row (negligible).

#define BATCH      1024
#define NHID       128
#define NCLASSES   320
#define PER_CLASS  320
#define ROW_OUT    (NCLASSES * PER_CLASS)   // 102400
#define ROW_OUT4   (ROW_OUT / 4)            // 25600
#define PC4        (PER_CLASS / 4)          // 80 float4 per class
#define NTHREADS   256

__global__ __launch_bounds__(NTHREADS) void hs_kernel(
    const float* __restrict__ in,     // [1024, 128]
    const float* __restrict__ Wtop,   // [128, 320]
    const float* __restrict__ btop,   // [320]
    const float* __restrict__ Wbot,   // [320, 128]
    const float* __restrict__ bbot,   // [320]
    float* __restrict__ out)          // [1024, 102400]
{
    __shared__ float in_s[NHID];
    __shared__ float top_s[NCLASSES];
    __shared__ float bot_s[PER_CLASS];

    const int b   = blockIdx.x;
    const int tid = threadIdx.x;

    // Load the input row (128 floats) into smem, vectorized.
    if (tid < NHID / 4) {
        reinterpret_cast<float4*>(in_s)[tid] =
            reinterpret_cast<const float4*>(in + (size_t)b * NHID)[tid];
    }
    __syncthreads();

    // Compute 320 top logits + 320 bottom logits. 640 dots of length 128.
    // j in [0,320): top column j (Wtop column-strided, coalesced across threads).
    // j in [320,640): bottom row j-320 (Wbot row contiguous per thread; L2-resident).
    for (int j = tid; j < NCLASSES + PER_CLASS; j += NTHREADS) {
        float sum;
        if (j < NCLASSES) {
            sum = btop[j];
            const float* w = Wtop + j;
            #pragma unroll 8
            for (int k = 0; k < NHID; k++)
                sum = fmaf(in_s[k], w[k * NCLASSES], sum);
            top_s[j] = sum;
        } else {
            const int t = j - NCLASSES;
            sum = bbot[t];
            const float4* w4 = reinterpret_cast<const float4*>(Wbot + (size_t)t * NHID);
            #pragma unroll 8
            for (int k = 0; k < NHID / 4; k++) {
                float4 w = w4[k];
                sum = fmaf(in_s[4 * k + 0], w.x, sum);
                sum = fmaf(in_s[4 * k + 1], w.y, sum);
                sum = fmaf(in_s[4 * k + 2], w.z, sum);
                sum = fmaf(in_s[4 * k + 3], w.w, sum);
            }
            bot_s[t] = sum;
        }
    }
    __syncthreads();

    // Stream the output row: 25600 coalesced float4 stores.
    float4* __restrict__ out4 = reinterpret_cast<float4*>(out + (size_t)b * ROW_OUT);
    const float4* __restrict__ bot4 = reinterpret_cast<const float4*>(bot_s);

    #pragma unroll 4
    for (int i = tid; i < ROW_OUT4; i += NTHREADS) {
        const int c  = i / PC4;     // class index (const-div -> mul.hi)
        const int t4 = i - c * PC4; // float4 index within class
        const float tv = top_s[c];
        float4 v = bot4[t4];
        v.x += tv; v.y += tv; v.z += tv; v.w += tv;
        out4[i] = v;
    }
}

extern "C" void kernel_launch(void* const* d_in, const int* in_sizes, int n_in,
                              void* d_out, int out_size) {
    const float* in   = (const float*)d_in[0];
    const float* Wtop = (const float*)d_in[1];
    const float* btop = (const float*)d_in[2];
    const float* Wbot = (const float*)d_in[3];
    const float* bbot = (const float*)d_in[4];
    float* out = (float*)d_out;

    hs_kernel<<<BATCH, NTHREADS>>>(in, Wtop, btop, Wbot, bbot, out);
}